// round 4
// baseline (speedup 1.0000x reference)
#include <cuda_runtime.h>
#include <math.h>

#define NE     200000
#define NI     100000
#define DIM    64
#define NEDGE  1500000
#define KEDGE  256
#define KITEM  100
#define SCALE  0.08838834764831845f   // 1/(2*sqrt(32))

#define CAND_MAX 2048

// fused topk kernel: 592 blocks = 148 SM x 4 (guaranteed co-resident)
#define TE_BLOCKS 512
#define TI_BLOCKS 80
#define NB_TOTAL  (TE_BLOCKS + TI_BLOCKS)     // 592
#define TE_STRIDE (TE_BLOCKS * 256)           // 131072
#define TE_ITEMS  12                          // 12*131072 >= NEDGE
#define TI_STRIDE (TI_BLOCKS * 256)           // 20480
#define TI_ITEMS  5                           // 5*20480 >= NI

// ---------------- scratch ----------------
__device__ float    g_proj[NE * DIM];
__device__ float    g_ex[NEDGE];
__device__ float    g_dd[2 * NE];             // [denom, deg]
__device__ float    g_sumnode[NE];

__device__ unsigned g_hist_e[65536];
__device__ unsigned g_hist_i[65536];
__device__ unsigned g_super_e[256];
__device__ unsigned g_super_i[256];
__device__ unsigned g_kth_e, g_kth_i;
__device__ int      g_cnt[2];
__device__ unsigned long long g_cand_e[CAND_MAX];
__device__ unsigned long long g_cand_i[CAND_MAX];

__device__ unsigned g_bar_cnt;                // zero-init
__device__ volatile unsigned g_bar_gen;       // zero-init

// ---------------- helpers ----------------
__device__ __forceinline__ unsigned fkey(float f) {
    unsigned u = __float_as_uint(f);
    return (u & 0x80000000u) ? ~u : (u | 0x80000000u);
}
__device__ __forceinline__ float keyf(unsigned k) {
    unsigned u = (k & 0x80000000u) ? (k & 0x7FFFFFFFu) : ~k;
    return __uint_as_float(u);
}

__device__ __forceinline__ void grid_sync() {
    __threadfence();
    __syncthreads();
    if (threadIdx.x == 0) {
        unsigned gen = g_bar_gen;
        if (atomicAdd(&g_bar_cnt, 1u) == gridDim.x - 1) {
            g_bar_cnt = 0u;
            __threadfence();
            g_bar_gen = gen + 1u;
        } else {
            while (g_bar_gen == gen) { __nanosleep(64); }
        }
        __threadfence();
    }
    __syncthreads();
}

// one block: pick 16-bit prefix P s.t. count(top16 > P) < K <= count(top16 >= P)
__device__ void select_kth(volatile unsigned* bins, volatile unsigned* super,
                           int K, unsigned* out_kth) {
    __shared__ unsigned s_c[256], s_sum[256];
    __shared__ int s_sel, s_krem;
    int t = threadIdx.x;
    // level 1: super-bins (top 8 bits)
    unsigned c = super[t];
    s_c[t] = c; s_sum[t] = c;
    __syncthreads();
    #pragma unroll
    for (int off = 1; off < 256; off <<= 1) {
        unsigned v = s_sum[t];
        if (t + off < 256) v += s_sum[t + off];
        __syncthreads();
        s_sum[t] = v;
        __syncthreads();
    }
    {
        unsigned incl = s_sum[t], excl = incl - s_c[t];
        if ((int)excl < K && K <= (int)incl) { s_sel = t; s_krem = K - (int)excl; }
    }
    __syncthreads();
    int sb = s_sel, kRem = s_krem;
    // level 2: the 256 bins of the selected super-bin
    c = bins[(sb << 8) + t];
    s_c[t] = c; s_sum[t] = c;
    __syncthreads();
    #pragma unroll
    for (int off = 1; off < 256; off <<= 1) {
        unsigned v = s_sum[t];
        if (t + off < 256) v += s_sum[t + off];
        __syncthreads();
        s_sum[t] = v;
        __syncthreads();
    }
    {
        unsigned incl = s_sum[t], excl = incl - s_c[t];
        if ((int)excl < kRem && kRem <= (int)incl)
            *out_kth = ((unsigned)((sb << 8) | t)) << 16;
    }
}

// one block: bitonic-sort candidates (value desc, idx asc), emit top K
__device__ void sort_emit(unsigned long long* cand, volatile int* cntp,
                          float* __restrict__ outV, float* __restrict__ outI, int K) {
    __shared__ unsigned long long s[CAND_MAX];
    int cnt = *cntp;
    if (cnt > CAND_MAX) cnt = CAND_MAX;
    int n2 = 1; while (n2 < cnt) n2 <<= 1;
    for (int i = threadIdx.x; i < n2; i += 256)
        s[i] = (i < cnt) ? ((volatile unsigned long long*)cand)[i]
                         : 0xFFFFFFFFFFFFFFFFull;
    __syncthreads();
    for (int k = 2; k <= n2; k <<= 1) {
        for (int j = k >> 1; j > 0; j >>= 1) {
            for (int i = threadIdx.x; i < n2; i += 256) {
                int p = i ^ j;
                if (p > i) {
                    bool up = ((i & k) == 0);
                    unsigned long long a = s[i], b = s[p];
                    if ((a > b) == up) { s[i] = b; s[p] = a; }
                }
            }
            __syncthreads();
        }
    }
    for (int t = threadIdx.x; t < K; t += 256) {
        unsigned long long cc = s[t];
        outV[t] = keyf(~(unsigned)(cc >> 32));
        outI[t] = (float)(unsigned)(cc & 0xFFFFFFFFu);
    }
}

// ---------------- 1) projection (+ fused init of all topk state) ------------
__global__ void k_proj(const float* __restrict__ emb, const float* __restrict__ W) {
    __shared__ float sE[64 * 64];
    __shared__ float sW[64 * 64];
    int tid = threadIdx.x;               // 128
    int base = blockIdx.x * 64 * DIM;
    int eb = blockIdx.x * 64;

    g_dd[2 * eb + tid] = 0.0f;
    if (tid < 64) g_sumnode[eb + tid] = 0.0f;
    if (blockIdx.x < 256) {
        int b = blockIdx.x << 8;
        #pragma unroll
        for (int i = tid; i < 256; i += 128) { g_hist_e[b + i] = 0u; g_hist_i[b + i] = 0u; }
    } else if (blockIdx.x == 256) {
        #pragma unroll
        for (int i = tid; i < 256; i += 128) { g_super_e[i] = 0u; g_super_i[i] = 0u; }
        if (tid == 0) { g_cnt[0] = 0; g_cnt[1] = 0; }
    }

    const float4* ev = (const float4*)(emb + base);
    const float4* wv = (const float4*)W;
    float4* sev = (float4*)sE;
    float4* swv = (float4*)sW;
    #pragma unroll
    for (int i = tid; i < 1024; i += 128) { sev[i] = ev[i]; swv[i] = wv[i]; }
    __syncthreads();

    int tr = tid >> 4;
    int tc = tid & 15;
    float acc[8][4];
    #pragma unroll
    for (int i = 0; i < 8; i++)
        #pragma unroll
        for (int j = 0; j < 4; j++) acc[i][j] = 0.0f;

    #pragma unroll 8
    for (int d = 0; d < 64; d++) {
        float4 w = *(const float4*)&sW[d * 64 + tc * 4];
        #pragma unroll
        for (int i = 0; i < 8; i++) {
            float e = sE[(tr * 8 + i) * 64 + d];
            acc[i][0] += e * w.x; acc[i][1] += e * w.y;
            acc[i][2] += e * w.z; acc[i][3] += e * w.w;
        }
    }
    #pragma unroll
    for (int i = 0; i < 8; i++)
        *(float4*)&g_proj[base + (tr * 8 + i) * 64 + tc * 4] =
            make_float4(acc[i][0], acc[i][1], acc[i][2], acc[i][3]);
}

// ---------------- 2) warp-cooperative per-edge (16 lanes/edge) --------------
__global__ void k_edge(const int* __restrict__ head, const int* __restrict__ tail,
                       const int* __restrict__ etype, const float* __restrict__ rel) {
    int warp_global = (blockIdx.x * blockDim.x + threadIdx.x) >> 5;
    int lane = threadIdx.x & 31;
    int half = lane >> 4;
    int sub  = lane & 15;
    int e = warp_global * 2 + half;

    int h = __ldg(&head[e]);
    int t = __ldg(&tail[e]);
    int r = __ldg(&etype[e]) - 1;

    float4 q  = *(const float4*)&g_proj[((size_t)h << 6) + (sub << 2)];
    float4 kv = *(const float4*)&g_proj[((size_t)t << 6) + (sub << 2)];
    float4 rv = __ldg((const float4*)rel + ((size_t)r << 4) + sub);

    float s = q.x * kv.x * rv.x + q.y * kv.y * rv.y
            + q.z * kv.z * rv.z + q.w * kv.w * rv.w;
    s += __shfl_xor_sync(0xffffffffu, s, 8);
    s += __shfl_xor_sync(0xffffffffu, s, 4);
    s += __shfl_xor_sync(0xffffffffu, s, 2);
    s += __shfl_xor_sync(0xffffffffu, s, 1);

    float lg = s * SCALE;
    float ex = __expf(lg);

    if (sub == 0) { g_ex[e] = ex; atomicAdd(&g_dd[2 * h], ex); }
    else if (sub == 1) atomicAdd(&g_dd[2 * h + 1], 1.0f);
    else if (sub == 2) atomicAdd(&g_sumnode[h], lg);
    else if (sub == 3) atomicAdd(&g_sumnode[t], lg);
}

// accurate-cheap -log(u): series near 1 (MUFU absolute error would wreck the
// top gumbel candidates), __logf elsewhere
__device__ __forceinline__ float neglog(float u) {
    float t = u - 1.0f;
    // -(t - t^2/2 + t^3/3 - t^4/4 + t^5/5 - t^6/6)
    float p = fmaf(t, -0.16666667f, 0.2f);
    p = fmaf(t, p, -0.25f);
    p = fmaf(t, p, 0.33333333f);
    p = fmaf(t, p, -0.5f);
    p = fmaf(t, p, 1.0f);
    float ser = -t * p;
    float fast = -__logf(u);
    return (u > 0.84f) ? ser : fast;
}

// ---------------- 3) ONE fused topk kernel: edges + items, 3 grid syncs ------
__global__ void __launch_bounds__(256, 4)
k_topk(const int* __restrict__ head, const float* __restrict__ noise,
       float* __restrict__ out,
       float* __restrict__ tkv, float* __restrict__ tki,
       float* __restrict__ itv, float* __restrict__ iti) {
    __shared__ unsigned sh[256];
    unsigned key[TE_ITEMS];
    int tid = threadIdx.x;
    bool isE = blockIdx.x < TE_BLOCKS;

    sh[tid] = 0u;
    __syncthreads();

    // ---- phase A: keys + 64k-bin hist + smem super-hist ----
    if (isE) {
        int gtid = blockIdx.x * 256 + tid;
        #pragma unroll
        for (int i = 0; i < TE_ITEMS; i++) {
            int e = gtid + i * TE_STRIDE;
            key[i] = 0u;
            if (e < NEDGE) {
                int h = __ldg(&head[e]);
                float2 dd = *(const float2*)&g_dd[2 * h];   // (denom, deg)
                float sc = __ldg(&g_ex[e]) * dd.y * __frcp_rn(dd.x);
                out[e] = sc;
                float x = neglog(__ldg(&noise[e]));          // -log(u)
                float ns = sc - __logf(x);                   // + gumbel
                unsigned k = fkey(ns);
                key[i] = k;
                atomicAdd(&g_hist_e[k >> 16], 1u);
                atomicAdd(&sh[k >> 24], 1u);
            }
        }
        __syncthreads();
        { unsigned c = sh[tid]; if (c) atomicAdd(&g_super_e[tid], c); }
    } else {
        int gtid = (blockIdx.x - TE_BLOCKS) * 256 + tid;
        #pragma unroll
        for (int i = 0; i < TI_ITEMS; i++) {
            int e = gtid + i * TI_STRIDE;
            key[i] = 0u;
            if (e < NI) {
                unsigned k = fkey(__ldg(&g_sumnode[e]));
                key[i] = k;
                atomicAdd(&g_hist_i[k >> 16], 1u);
                atomicAdd(&sh[k >> 24], 1u);
            }
        }
        __syncthreads();
        { unsigned c = sh[tid]; if (c) atomicAdd(&g_super_i[tid], c); }
    }
    grid_sync();

    // ---- phase B: select 16-bit threshold (2 blocks work, rest wait) ----
    if (blockIdx.x == 0)              select_kth(g_hist_e, g_super_e, KEDGE, &g_kth_e);
    else if (blockIdx.x == TE_BLOCKS) select_kth(g_hist_i, g_super_i, KITEM, &g_kth_i);
    grid_sync();

    // ---- phase C: collect candidates >= threshold ----
    if (isE) {
        unsigned kth = *(volatile unsigned*)&g_kth_e;
        int gtid = blockIdx.x * 256 + tid;
        #pragma unroll
        for (int i = 0; i < TE_ITEMS; i++) {
            unsigned k = key[i];
            if (k >= kth) {
                int p = atomicAdd(&g_cnt[0], 1);
                if (p < CAND_MAX)
                    g_cand_e[p] = (((unsigned long long)(~k)) << 32)
                                | (unsigned)(gtid + i * TE_STRIDE);
            }
        }
    } else {
        unsigned kth = *(volatile unsigned*)&g_kth_i;
        int gtid = (blockIdx.x - TE_BLOCKS) * 256 + tid;
        #pragma unroll
        for (int i = 0; i < TI_ITEMS; i++) {
            unsigned k = key[i];
            if (k >= kth) {
                int p = atomicAdd(&g_cnt[1], 1);
                if (p < CAND_MAX)
                    g_cand_i[p] = (((unsigned long long)(~k)) << 32)
                                | (unsigned)(gtid + i * TI_STRIDE);
            }
        }
    }
    grid_sync();

    // ---- phase D: sort + emit (2 blocks) ----
    if (blockIdx.x == 0)              sort_emit(g_cand_e, &g_cnt[0], tkv, tki, KEDGE);
    else if (blockIdx.x == TE_BLOCKS) sort_emit(g_cand_i, &g_cnt[1], itv, iti, KITEM);
}

// ---------------- host ----------------
extern "C" void kernel_launch(void* const* d_in, const int* in_sizes, int n_in,
                              void* d_out, int out_size) {
    const float* emb   = (const float*)d_in[0];
    const float* WQ    = (const float*)d_in[1];
    const float* rel   = (const float*)d_in[2];
    const float* noise = (const float*)d_in[3];
    const int*   eidx  = (const int*)d_in[4];
    const int*   etype = (const int*)d_in[5];
    const int* head = eidx;
    const int* tail = eidx + NEDGE;
    float* out = (float*)d_out;

    float* out_tkv = out + NEDGE;
    float* out_tki = out + NEDGE + KEDGE;
    float* out_itv = out + NEDGE + 2 * KEDGE;
    float* out_iti = out + NEDGE + 2 * KEDGE + KITEM;

    k_proj<<<NE / 64, 128>>>(emb, WQ);
    k_edge<<<NEDGE / 16, 256>>>(head, tail, etype, rel);
    k_topk<<<NB_TOTAL, 256>>>(head, noise, out, out_tkv, out_tki, out_itv, out_iti);
}

// round 5
// speedup vs baseline: 2.0879x; 2.0879x over previous
#include <cuda_runtime.h>
#include <math.h>

#define NE     200000
#define NI     100000
#define DIM    64
#define NEDGE  1500000
#define KEDGE  256
#define KITEM  100
#define SCALE  0.08838834764831845f   // 1/(2*sqrt(32))

#define CAND_MAX 2048
#define NBINS    8192                 // 13-bit key prefix
#define BIN_SHIFT 19

// fused topk kernel: 592 blocks = 148 SM x 4 (guaranteed co-resident)
#define TE_BLOCKS 512
#define TI_BLOCKS 80
#define NB_TOTAL  (TE_BLOCKS + TI_BLOCKS)
#define TE_STRIDE (TE_BLOCKS * 256)           // 131072
#define TE_ITEMS  12                          // 12*131072 >= NEDGE
#define TI_STRIDE (TI_BLOCKS * 256)           // 20480
#define TI_ITEMS  5                           // 5*20480 >= NI

// ---------------- scratch ----------------
__device__ float    g_proj[NE * DIM];
__device__ float    g_ex[NEDGE];
__device__ float    g_dd[2 * NE];             // [denom, deg]
__device__ float    g_sumnode[NE];

__device__ unsigned g_bins_e[NBINS];
__device__ unsigned g_bins_i[NBINS];
__device__ unsigned g_kth_e, g_kth_i;
__device__ int      g_cnt[2];
__device__ unsigned long long g_cand_e[CAND_MAX];
__device__ unsigned long long g_cand_i[CAND_MAX];

__device__ unsigned g_bar_cnt;                // zero-init, self-resetting
__device__ volatile unsigned g_bar_gen;

// ---------------- helpers ----------------
__device__ __forceinline__ unsigned fkey(float f) {
    unsigned u = __float_as_uint(f);
    return (u & 0x80000000u) ? ~u : (u | 0x80000000u);
}
__device__ __forceinline__ float keyf(unsigned k) {
    unsigned u = (k & 0x80000000u) ? (k & 0x7FFFFFFFu) : ~k;
    return __uint_as_float(u);
}

#define PACK2(out, lo, hi) \
    asm("mov.b64 %0, {%1, %2};" : "=l"(out) : "f"(lo), "f"(hi))
#define UNPACK2(lo, hi, in) \
    asm("mov.b64 {%0, %1}, %2;" : "=f"(lo), "=f"(hi) : "l"(in))
#define FMA2(d, a, b, c) \
    asm("fma.rn.f32x2 %0, %1, %2, %3;" : "=l"(d) : "l"(a), "l"(b), "l"(c))

__device__ __forceinline__ void grid_sync() {
    __threadfence();
    __syncthreads();
    if (threadIdx.x == 0) {
        unsigned gen = g_bar_gen;
        if (atomicAdd(&g_bar_cnt, 1u) == gridDim.x - 1) {
            g_bar_cnt = 0u;
            __threadfence();
            g_bar_gen = gen + 1u;
        } else {
            while (g_bar_gen == gen) { __nanosleep(64); }
        }
        __threadfence();
    }
    __syncthreads();
}

// one block: find 13-bit prefix bin of the Kth-largest key
__device__ void select13(volatile unsigned* bins, int K, unsigned* out_kth) {
    __shared__ unsigned s_sum[256];
    __shared__ unsigned s_kth;
    int t = threadIdx.x;
    unsigned sum = 0;
    #pragma unroll
    for (int i = 0; i < 32; i++) sum += bins[t * 32 + i];
    s_sum[t] = sum;
    __syncthreads();
    // suffix sum over thread chunks
    #pragma unroll
    for (int off = 1; off < 256; off <<= 1) {
        unsigned v = s_sum[t];
        if (t + off < 256) v += s_sum[t + off];
        __syncthreads();
        s_sum[t] = v;
        __syncthreads();
    }
    unsigned incl = s_sum[t];           // chunks t..255
    unsigned above = incl - sum;        // chunks above this one
    if ((int)above < K && K <= (int)incl) {     // exactly one thread
        unsigned run = above;
        for (int i = 31; i >= 0; i--) {
            run += bins[t * 32 + i];
            if ((int)run >= K) { s_kth = (unsigned)(t * 32 + i) << BIN_SHIFT; break; }
        }
    }
    __syncthreads();
    if (t == 0) *out_kth = s_kth;
}

// one block: bitonic-sort candidates (value desc, idx asc), emit top K
__device__ void sort_emit(unsigned long long* s, unsigned long long* cand,
                          volatile int* cntp,
                          float* __restrict__ outV, float* __restrict__ outI, int K) {
    int cnt = *cntp;
    if (cnt > CAND_MAX) cnt = CAND_MAX;
    int n2 = 1; while (n2 < cnt) n2 <<= 1;
    for (int i = threadIdx.x; i < n2; i += 256)
        s[i] = (i < cnt) ? ((volatile unsigned long long*)cand)[i]
                         : 0xFFFFFFFFFFFFFFFFull;
    __syncthreads();
    for (int k = 2; k <= n2; k <<= 1) {
        for (int j = k >> 1; j > 0; j >>= 1) {
            for (int i = threadIdx.x; i < n2; i += 256) {
                int p = i ^ j;
                if (p > i) {
                    bool up = ((i & k) == 0);
                    unsigned long long a = s[i], b = s[p];
                    if ((a > b) == up) { s[i] = b; s[p] = a; }
                }
            }
            __syncthreads();
        }
    }
    for (int t = threadIdx.x; t < K; t += 256) {
        unsigned long long cc = s[t];
        outV[t] = keyf(~(unsigned)(cc >> 32));
        outI[t] = (float)(unsigned)(cc & 0xFFFFFFFFu);
    }
}

// ---------------- 1) projection, packed f32x2 FMA (+ fused init) ------------
__global__ void k_proj(const float* __restrict__ emb, const float* __restrict__ W) {
    __shared__ float sE[64 * 68];        // padded stride 68
    __shared__ float sW[64 * 64];
    int tid = threadIdx.x;               // 128
    int base = blockIdx.x * 64 * DIM;
    int eb = blockIdx.x * 64;

    // fused init of all global scratch
    g_dd[2 * eb + tid] = 0.0f;
    if (tid < 64) g_sumnode[eb + tid] = 0.0f;
    if (blockIdx.x < 64)        g_bins_e[blockIdx.x * 128 + tid] = 0u;
    else if (blockIdx.x < 128)  g_bins_i[(blockIdx.x - 64) * 128 + tid] = 0u;
    else if (blockIdx.x == 128 && tid < 2) g_cnt[tid] = 0;

    const float4* ev = (const float4*)(emb + base);
    const float4* wv = (const float4*)W;
    #pragma unroll
    for (int i = tid; i < 1024; i += 128) {
        int r = i >> 4, c = i & 15;
        *(float4*)&sE[r * 68 + c * 4] = ev[i];
        ((float4*)sW)[i] = wv[i];
    }
    __syncthreads();

    int tr = tid >> 4;   // 0..7 -> rows tr*8..tr*8+7
    int tc = tid & 15;   // cols tc*4..tc*4+3

    unsigned long long a01[8], a23[8];
    #pragma unroll
    for (int i = 0; i < 8; i++) { a01[i] = 0ull; a23[i] = 0ull; }

    #pragma unroll
    for (int d4 = 0; d4 < 16; d4++) {
        unsigned long long w01[4], w23[4];
        #pragma unroll
        for (int j = 0; j < 4; j++) {
            float4 w = *(const float4*)&sW[(d4 * 4 + j) * 64 + tc * 4];
            PACK2(w01[j], w.x, w.y);
            PACK2(w23[j], w.z, w.w);
        }
        #pragma unroll
        for (int i = 0; i < 8; i++) {
            float4 e = *(const float4*)&sE[(tr * 8 + i) * 68 + d4 * 4];
            unsigned long long ee;
            PACK2(ee, e.x, e.x); FMA2(a01[i], ee, w01[0], a01[i]); FMA2(a23[i], ee, w23[0], a23[i]);
            PACK2(ee, e.y, e.y); FMA2(a01[i], ee, w01[1], a01[i]); FMA2(a23[i], ee, w23[1], a23[i]);
            PACK2(ee, e.z, e.z); FMA2(a01[i], ee, w01[2], a01[i]); FMA2(a23[i], ee, w23[2], a23[i]);
            PACK2(ee, e.w, e.w); FMA2(a01[i], ee, w01[3], a01[i]); FMA2(a23[i], ee, w23[3], a23[i]);
        }
    }
    #pragma unroll
    for (int i = 0; i < 8; i++) {
        float4 o;
        UNPACK2(o.x, o.y, a01[i]);
        UNPACK2(o.z, o.w, a23[i]);
        *(float4*)&g_proj[base + (tr * 8 + i) * 64 + tc * 4] = o;
    }
}

// ---------------- 2) warp-cooperative per-edge (16 lanes/edge) --------------
__global__ void k_edge(const int* __restrict__ head, const int* __restrict__ tail,
                       const int* __restrict__ etype, const float* __restrict__ rel) {
    int warp_global = (blockIdx.x * blockDim.x + threadIdx.x) >> 5;
    int lane = threadIdx.x & 31;
    int half = lane >> 4;
    int sub  = lane & 15;
    int e = warp_global * 2 + half;

    int h = __ldg(&head[e]);
    int t = __ldg(&tail[e]);
    int r = __ldg(&etype[e]) - 1;

    float4 q  = *(const float4*)&g_proj[((size_t)h << 6) + (sub << 2)];
    float4 kv = *(const float4*)&g_proj[((size_t)t << 6) + (sub << 2)];
    float4 rv = __ldg((const float4*)rel + ((size_t)r << 4) + sub);

    float s = q.x * kv.x * rv.x + q.y * kv.y * rv.y
            + q.z * kv.z * rv.z + q.w * kv.w * rv.w;
    s += __shfl_xor_sync(0xffffffffu, s, 8);
    s += __shfl_xor_sync(0xffffffffu, s, 4);
    s += __shfl_xor_sync(0xffffffffu, s, 2);
    s += __shfl_xor_sync(0xffffffffu, s, 1);

    float lg = s * SCALE;
    float ex = __expf(lg);

    if (sub == 0) { g_ex[e] = ex; atomicAdd(&g_dd[2 * h], ex); }
    else if (sub == 1) atomicAdd(&g_dd[2 * h + 1], 1.0f);
    else if (sub == 2) atomicAdd(&g_sumnode[h], lg);
    else if (sub == 3) atomicAdd(&g_sumnode[t], lg);
}

// accurate-cheap -log(u): series near 1 (MUFU abs error would wreck the top
// gumbel candidates where x = -log u ~ 1e-6), __logf elsewhere
__device__ __forceinline__ float neglog(float u) {
    float t = u - 1.0f;
    float p = fmaf(t, -0.16666667f, 0.2f);
    p = fmaf(t, p, -0.25f);
    p = fmaf(t, p, 0.33333333f);
    p = fmaf(t, p, -0.5f);
    p = fmaf(t, p, 1.0f);
    float ser = -t * p;
    float fast = -__logf(u);
    return (u > 0.84f) ? ser : fast;
}

// warp-aggregated smem histogram add (keys are highly concentrated)
__device__ __forceinline__ void hist_add(unsigned* sh, unsigned bin) {
    unsigned m = __match_any_sync(0xffffffffu, bin);
    int leader = __ffs(m) - 1;
    if ((int)(threadIdx.x & 31) == leader) atomicAdd(&sh[bin], __popc(m));
}

// ---------------- 3) fused topk (edges + items), 3 grid syncs ---------------
__global__ void __launch_bounds__(256, 4)
k_topk(const int* __restrict__ head, const float* __restrict__ noise,
       float* __restrict__ out,
       float* __restrict__ tkv, float* __restrict__ tki,
       float* __restrict__ itv, float* __restrict__ iti) {
    __shared__ unsigned long long s_buf[NBINS / 2];   // 32KB: hist, then sort
    unsigned* s_hist = (unsigned*)s_buf;
    unsigned key[TE_ITEMS];
    int tid = threadIdx.x;
    bool isE = blockIdx.x < TE_BLOCKS;

    #pragma unroll
    for (int i = 0; i < NBINS / 256; i++) s_hist[tid + i * 256] = 0u;
    __syncthreads();

    // ---- phase A: keys + warp-aggregated 13-bit smem hist ----
    if (isE) {
        int gtid = blockIdx.x * 256 + tid;
        #pragma unroll
        for (int i = 0; i < TE_ITEMS; i++) {
            int e = gtid + i * TE_STRIDE;
            unsigned k = 0u;
            if (e < NEDGE) {
                int h = __ldg(&head[e]);
                float2 dd = *(const float2*)&g_dd[2 * h];   // (denom, deg)
                float sc = __ldg(&g_ex[e]) * dd.y * __frcp_rn(dd.x);
                out[e] = sc;
                float x = neglog(__ldg(&noise[e]));          // -log(u)
                k = fkey(sc - __logf(x));                    // + gumbel
            }
            key[i] = k;
            hist_add(s_hist, k >> BIN_SHIFT);   // OOB lanes count into bin 0 (harmless)
        }
        __syncthreads();
        #pragma unroll
        for (int i = 0; i < NBINS / 256; i++) {
            unsigned c = s_hist[tid + i * 256];
            if (c) atomicAdd(&g_bins_e[tid + i * 256], c);
        }
    } else {
        int gtid = (blockIdx.x - TE_BLOCKS) * 256 + tid;
        #pragma unroll
        for (int i = 0; i < TI_ITEMS; i++) {
            int e = gtid + i * TI_STRIDE;
            unsigned k = (e < NI) ? fkey(__ldg(&g_sumnode[e])) : 0u;
            key[i] = k;
            hist_add(s_hist, k >> BIN_SHIFT);
        }
        __syncthreads();
        #pragma unroll
        for (int i = 0; i < NBINS / 256; i++) {
            unsigned c = s_hist[tid + i * 256];
            if (c) atomicAdd(&g_bins_i[tid + i * 256], c);
        }
    }
    grid_sync();

    // ---- phase B: threshold select (2 blocks; others wait at next barrier) --
    if (blockIdx.x == 0)              select13(g_bins_e, KEDGE, &g_kth_e);
    else if (blockIdx.x == TE_BLOCKS) select13(g_bins_i, KITEM, &g_kth_i);
    grid_sync();

    // ---- phase C: collect candidates >= threshold ----
    if (isE) {
        unsigned kth = *(volatile unsigned*)&g_kth_e;
        int gtid = blockIdx.x * 256 + tid;
        #pragma unroll
        for (int i = 0; i < TE_ITEMS; i++) {
            unsigned k = key[i];
            if (k >= kth) {
                int p = atomicAdd(&g_cnt[0], 1);
                if (p < CAND_MAX)
                    g_cand_e[p] = (((unsigned long long)(~k)) << 32)
                                | (unsigned)(gtid + i * TE_STRIDE);
            }
        }
    } else {
        unsigned kth = *(volatile unsigned*)&g_kth_i;
        int gtid = (blockIdx.x - TE_BLOCKS) * 256 + tid;
        #pragma unroll
        for (int i = 0; i < TI_ITEMS; i++) {
            unsigned k = key[i];
            if (k >= kth) {
                int p = atomicAdd(&g_cnt[1], 1);
                if (p < CAND_MAX)
                    g_cand_i[p] = (((unsigned long long)(~k)) << 32)
                                | (unsigned)(gtid + i * TI_STRIDE);
            }
        }
    }
    grid_sync();

    // ---- phase D: sort + emit (2 blocks) ----
    if (blockIdx.x == 0)
        sort_emit(s_buf, g_cand_e, &g_cnt[0], tkv, tki, KEDGE);
    else if (blockIdx.x == TE_BLOCKS)
        sort_emit(s_buf, g_cand_i, &g_cnt[1], itv, iti, KITEM);
}

// ---------------- host ----------------
extern "C" void kernel_launch(void* const* d_in, const int* in_sizes, int n_in,
                              void* d_out, int out_size) {
    const float* emb   = (const float*)d_in[0];
    const float* WQ    = (const float*)d_in[1];
    const float* rel   = (const float*)d_in[2];
    const float* noise = (const float*)d_in[3];
    const int*   eidx  = (const int*)d_in[4];
    const int*   etype = (const int*)d_in[5];
    const int* head = eidx;
    const int* tail = eidx + NEDGE;
    float* out = (float*)d_out;

    float* out_tkv = out + NEDGE;
    float* out_tki = out + NEDGE + KEDGE;
    float* out_itv = out + NEDGE + 2 * KEDGE;
    float* out_iti = out + NEDGE + 2 * KEDGE + KITEM;

    k_proj<<<NE / 64, 128>>>(emb, WQ);
    k_edge<<<NEDGE / 16, 256>>>(head, tail, etype, rel);
    k_topk<<<NB_TOTAL, 256>>>(head, noise, out, out_tkv, out_tki, out_itv, out_iti);
}